// round 15
// baseline (speedup 1.0000x reference)
#include <cuda_runtime.h>
#include <cuda_fp16.h>

#define N_NODES 50000
#define N_EDGES 1000000
#define D_IN    64
#define D_HID   64
#define D_OUTF  32

// ---- scratch (no allocs). Device globals referenced ONLY in device code. ----
// Aggregation buffers are SPLIT (2 partial-sum banks) to halve fp16
// accumulation error; banks are combined in fp32 at the consumer.
__device__ float  g_deg [N_NODES];
__device__ __align__(16) __half g_h16 [N_NODES * D_HID];        // hs fp16
__device__ __align__(16) __half g_agg [2 * N_NODES * D_HID];    // layer-1 agg banks
__device__ __align__(16) __half g_agg2[2 * N_NODES * D_OUTF];   // layer-2 agg banks

__device__ __forceinline__ unsigned int h2u(__half2 h) {
    return *reinterpret_cast<unsigned int*>(&h);
}

// fp16x2 vector reduction: adds 8 halves (16B) atomically.
__device__ __forceinline__ void red_add_v4h2(__half* p, unsigned int m0, unsigned int m1,
                                             unsigned int m2, unsigned int m3) {
    asm volatile("red.global.add.noftz.v4.f16x2 [%0], {%1, %2, %3, %4};"
                 :: "l"(p), "r"(m0), "r"(m1), "r"(m2), "r"(m3) : "memory");
}

// ---------------- degree ----------------
__global__ void k_deg_init() {
    int i = blockIdx.x * blockDim.x + threadIdx.x;
    if (i < N_NODES) g_deg[i] = 1.0f;          // self-loop weight
}

__global__ void k_deg_count(const int* __restrict__ dst, const float* __restrict__ w) {
    int t = blockIdx.x * blockDim.x + threadIdx.x;
    int e0 = t * 4;
#pragma unroll
    for (int j = 0; j < 4; j++) {
        int e = e0 + j;
        if (e < N_EDGES) atomicAdd(&g_deg[__ldg(&dst[e])], __ldg(&w[e]));
    }
}

// ---------------- GEMM L1 (64->64): 4x8 per thread ----------------
// Writes hs fp16 to g_h16, self-loop init to agg bank0, zeros to bank1.
__global__ __launch_bounds__(128) void k_gemm64(
        const float* __restrict__ X, const float* __restrict__ W) {
    constexpr int DI = 64, DO = 64;
    constexpr int TX = 8, ROWS = 64, XS = ROWS + 4;
    __shared__ float Ws [DI * DO];
    __shared__ float xsT[DI * XS];

    const int tid = threadIdx.x;
    const int tx  = tid % TX;
    const int ty  = tid / TX;
    const int blockRow = blockIdx.x * ROWS;

    for (int i = tid; i < DI * DO / 4; i += 128)
        reinterpret_cast<float4*>(Ws)[i] = reinterpret_cast<const float4*>(W)[i];

    for (int i = tid; i < ROWS * (DI / 4); i += 128) {
        int row = i / (DI / 4);
        int c4  = i % (DI / 4);
        int gr  = blockRow + row;
        float4 v = make_float4(0.f, 0.f, 0.f, 0.f);
        if (gr < N_NODES)
            v = reinterpret_cast<const float4*>(X + gr * DI)[c4];
        xsT[(c4 * 4 + 0) * XS + row] = v.x;
        xsT[(c4 * 4 + 1) * XS + row] = v.y;
        xsT[(c4 * 4 + 2) * XS + row] = v.z;
        xsT[(c4 * 4 + 3) * XS + row] = v.w;
    }
    __syncthreads();

    float acc[4][8];
#pragma unroll
    for (int i = 0; i < 4; i++)
#pragma unroll
        for (int j = 0; j < 8; j++) acc[i][j] = 0.0f;

#pragma unroll
    for (int k = 0; k < DI; k++) {
        float4 a  = *reinterpret_cast<const float4*>(&xsT[k * XS + ty * 4]);
        float4 b0 = *reinterpret_cast<const float4*>(&Ws [k * DO + tx * 8]);
        float4 b1 = *reinterpret_cast<const float4*>(&Ws [k * DO + tx * 8 + 4]);
        float av[4] = {a.x, a.y, a.z, a.w};
        float bv[8] = {b0.x, b0.y, b0.z, b0.w, b1.x, b1.y, b1.z, b1.w};
#pragma unroll
        for (int i = 0; i < 4; i++)
#pragma unroll
            for (int j = 0; j < 8; j++)
                acc[i][j] += av[i] * bv[j];
    }

#pragma unroll
    for (int i = 0; i < 4; i++) {
        int row = blockRow + ty * 4 + i;
        if (row >= N_NODES) break;
        float dv = rsqrtf(g_deg[row]);
        float v[8];
#pragma unroll
        for (int j = 0; j < 8; j++) v[j] = dv * acc[i][j];
        uint4 hp;
        hp.x = h2u(__float22half2_rn(make_float2(v[0], v[1])));
        hp.y = h2u(__float22half2_rn(make_float2(v[2], v[3])));
        hp.z = h2u(__float22half2_rn(make_float2(v[4], v[5])));
        hp.w = h2u(__float22half2_rn(make_float2(v[6], v[7])));
        *reinterpret_cast<uint4*>(&g_h16[row * DO + tx * 8]) = hp;
        *reinterpret_cast<uint4*>(&g_agg[row * DO + tx * 8]) = hp;              // bank0: self-loop
        *reinterpret_cast<uint4*>(&g_agg[N_NODES * DO + row * DO + tx * 8])
            = make_uint4(0u, 0u, 0u, 0u);                                       // bank1: zero
    }
}

// ---------------- GEMM L2 (64->32), input = fp32 combine of agg banks + final1 ----
__global__ __launch_bounds__(256) void k_gemm32(const float* __restrict__ W,
                                                const float* __restrict__ b1) {
    constexpr int DI = 64, DO = 32;
    constexpr int TX = 8, ROWS = 128, XS = ROWS + 4;
    __shared__ float Ws [DI * DO];
    __shared__ float xsT[DI * XS];

    const int tid = threadIdx.x;
    const int tx  = tid % TX;
    const int ty  = tid / TX;
    const int blockRow = blockIdx.x * ROWS;

    for (int i = tid; i < DI * DO / 4; i += 256)
        reinterpret_cast<float4*>(Ws)[i] = reinterpret_cast<const float4*>(W)[i];

    for (int i = tid; i < ROWS * (DI / 4); i += 256) {
        int row = i / (DI / 4);
        int c4  = i % (DI / 4);
        int gr  = blockRow + row;
        float4 v = make_float4(0.f, 0.f, 0.f, 0.f);
        if (gr < N_NODES) {
            uint2 r0 = reinterpret_cast<const uint2*>(g_agg + gr * DI)[c4];
            uint2 r1 = reinterpret_cast<const uint2*>(g_agg + N_NODES * DI + gr * DI)[c4];
            float2 a0 = __half22float2(*reinterpret_cast<__half2*>(&r0.x));
            float2 a1 = __half22float2(*reinterpret_cast<__half2*>(&r0.y));
            float2 c0 = __half22float2(*reinterpret_cast<__half2*>(&r1.x));
            float2 c1 = __half22float2(*reinterpret_cast<__half2*>(&r1.y));
            float  dv = rsqrtf(g_deg[gr]);
            float4 bb = __ldg(&reinterpret_cast<const float4*>(b1)[c4]);
            v.x = fmaxf(dv * (a0.x + c0.x) + bb.x, 0.0f);
            v.y = fmaxf(dv * (a0.y + c0.y) + bb.y, 0.0f);
            v.z = fmaxf(dv * (a1.x + c1.x) + bb.z, 0.0f);
            v.w = fmaxf(dv * (a1.y + c1.y) + bb.w, 0.0f);
        }
        xsT[(c4 * 4 + 0) * XS + row] = v.x;
        xsT[(c4 * 4 + 1) * XS + row] = v.y;
        xsT[(c4 * 4 + 2) * XS + row] = v.z;
        xsT[(c4 * 4 + 3) * XS + row] = v.w;
    }
    __syncthreads();

    float acc[4][4];
#pragma unroll
    for (int i = 0; i < 4; i++)
#pragma unroll
        for (int j = 0; j < 4; j++) acc[i][j] = 0.0f;

#pragma unroll
    for (int k = 0; k < DI; k++) {
        float4 a = *reinterpret_cast<const float4*>(&xsT[k * XS + ty * 4]);
        float4 b = *reinterpret_cast<const float4*>(&Ws [k * DO + tx * 4]);
        acc[0][0] += a.x * b.x; acc[0][1] += a.x * b.y; acc[0][2] += a.x * b.z; acc[0][3] += a.x * b.w;
        acc[1][0] += a.y * b.x; acc[1][1] += a.y * b.y; acc[1][2] += a.y * b.z; acc[1][3] += a.y * b.w;
        acc[2][0] += a.z * b.x; acc[2][1] += a.z * b.y; acc[2][2] += a.z * b.z; acc[2][3] += a.z * b.w;
        acc[3][0] += a.w * b.x; acc[3][1] += a.w * b.y; acc[3][2] += a.w * b.z; acc[3][3] += a.w * b.w;
    }

#pragma unroll
    for (int i = 0; i < 4; i++) {
        int row = blockRow + ty * 4 + i;
        if (row >= N_NODES) break;
        float dv = rsqrtf(g_deg[row]);
        uint2 hp;
        hp.x = h2u(__float22half2_rn(make_float2(dv * acc[i][0], dv * acc[i][1])));
        hp.y = h2u(__float22half2_rn(make_float2(dv * acc[i][2], dv * acc[i][3])));
        *reinterpret_cast<uint2*>(&g_h16 [row * DO + tx * 4]) = hp;
        *reinterpret_cast<uint2*>(&g_agg2[row * DO + tx * 4]) = hp;             // bank0: self-loop
        *reinterpret_cast<uint2*>(&g_agg2[N_NODES * DO + row * DO + tx * 4])
            = make_uint2(0u, 0u);                                               // bank1: zero
    }
}

// ---------------- edge scatter: fp16 read + fp16 vector RED, split banks ----------------
// D=64: TPE=8, lane covers 8 cols. Edge half A -> bank0, half B -> bank1.
__global__ void k_scatter64(const int* __restrict__ src,
                            const int* __restrict__ dst,
                            const float* __restrict__ w) {
    constexpr int TPE = 8, HALF = N_EDGES / 2;
    int tid = blockIdx.x * blockDim.x + threadIdx.x;
    int e = tid / TPE;
    int p = tid % TPE;
    if (e >= HALF) return;

#pragma unroll
    for (int half = 0; half < 2; half++) {
        int ee = e + half * HALF;
        int   s  = __ldg(&src[ee]);
        int   d  = __ldg(&dst[ee]);
        float we = __ldg(&w[ee]);
        uint4 hv = *reinterpret_cast<const uint4*>(&g_h16[s * 64 + p * 8]);
        float2 f0 = __half22float2(*reinterpret_cast<__half2*>(&hv.x));
        float2 f1 = __half22float2(*reinterpret_cast<__half2*>(&hv.y));
        float2 f2 = __half22float2(*reinterpret_cast<__half2*>(&hv.z));
        float2 f3 = __half22float2(*reinterpret_cast<__half2*>(&hv.w));
        unsigned int m0 = h2u(__float22half2_rn(make_float2(we*f0.x, we*f0.y)));
        unsigned int m1 = h2u(__float22half2_rn(make_float2(we*f1.x, we*f1.y)));
        unsigned int m2 = h2u(__float22half2_rn(make_float2(we*f2.x, we*f2.y)));
        unsigned int m3 = h2u(__float22half2_rn(make_float2(we*f3.x, we*f3.y)));
        red_add_v4h2(g_agg + half * N_NODES * 64 + d * 64 + p * 8, m0, m1, m2, m3);
    }
}

// D=32: TPE=4, lane covers 8 cols.
__global__ void k_scatter32(const int* __restrict__ src,
                            const int* __restrict__ dst,
                            const float* __restrict__ w) {
    constexpr int TPE = 4, HALF = N_EDGES / 2;
    int tid = blockIdx.x * blockDim.x + threadIdx.x;
    int e = tid / TPE;
    int p = tid % TPE;
    if (e >= HALF) return;

#pragma unroll
    for (int half = 0; half < 2; half++) {
        int ee = e + half * HALF;
        int   s  = __ldg(&src[ee]);
        int   d  = __ldg(&dst[ee]);
        float we = __ldg(&w[ee]);
        uint4 hv = *reinterpret_cast<const uint4*>(&g_h16[s * 32 + p * 8]);
        float2 f0 = __half22float2(*reinterpret_cast<__half2*>(&hv.x));
        float2 f1 = __half22float2(*reinterpret_cast<__half2*>(&hv.y));
        float2 f2 = __half22float2(*reinterpret_cast<__half2*>(&hv.z));
        float2 f3 = __half22float2(*reinterpret_cast<__half2*>(&hv.w));
        unsigned int m0 = h2u(__float22half2_rn(make_float2(we*f0.x, we*f0.y)));
        unsigned int m1 = h2u(__float22half2_rn(make_float2(we*f1.x, we*f1.y)));
        unsigned int m2 = h2u(__float22half2_rn(make_float2(we*f2.x, we*f2.y)));
        unsigned int m3 = h2u(__float22half2_rn(make_float2(we*f3.x, we*f3.y)));
        red_add_v4h2(g_agg2 + half * N_NODES * 32 + d * 32 + p * 8, m0, m1, m2, m3);
    }
}

// ---------------- finalize layer 2: OUT = relu(rsqrt(deg)*(bank0+bank1) + b2) ----------------
__global__ void k_final2(float* __restrict__ OUT, const float* __restrict__ b) {
    int i = blockIdx.x * blockDim.x + threadIdx.x;
    if (i >= N_NODES * D_OUTF) return;
    int row = i / D_OUTF, col = i % D_OUTF;
    float s = __half2float(g_agg2[i]) + __half2float(g_agg2[N_NODES * D_OUTF + i]);
    float v = rsqrtf(g_deg[row]) * s + b[col];
    OUT[i] = fmaxf(v, 0.0f);
}

extern "C" void kernel_launch(void* const* d_in, const int* in_sizes, int n_in,
                              void* d_out, int out_size) {
    const float* x   = (const float*)d_in[0];
    const int*   ei  = (const int*)  d_in[1];   // [2, E]
    const float* ew  = (const float*)d_in[2];
    const float* W1  = (const float*)d_in[3];
    const float* b1  = (const float*)d_in[4];
    const float* W2  = (const float*)d_in[5];
    const float* b2  = (const float*)d_in[6];
    float*       out = (float*)d_out;

    const int* src = ei;
    const int* dst = ei + N_EDGES;

    k_deg_init <<<(N_NODES + 255) / 256, 256>>>();
    k_deg_count<<<(N_EDGES / 4 + 255) / 256, 256>>>(dst, ew);

    // ---- layer 1 ----
    k_gemm64<<<(N_NODES + 63) / 64, 128>>>(x, W1);
    {
        int nthr = (N_EDGES / 2) * 8;
        k_scatter64<<<(nthr + 255) / 256, 256>>>(src, dst, ew);
    }

    // ---- layer 2 (final1 fused into gemm32 input) ----
    k_gemm32<<<(N_NODES + 127) / 128, 256>>>(W2, b1);
    {
        int nthr = (N_EDGES / 2) * 4;
        k_scatter32<<<(nthr + 255) / 256, 256>>>(src, dst, ew);
    }
    k_final2<<<(N_NODES * D_OUTF + 255) / 256, 256>>>(out, b2);
}